// round 3
// baseline (speedup 1.0000x reference)
#include <cuda_runtime.h>
#include <cstdint>

// Output: [B=4, D=160, H=192, W=224, 3] float32, row-major.
// out[b,d,h,w,i] = A[b,i,0]*x + A[b,i,1]*y + A[b,i,2]*z + t[b,i] - mesh_i
// with x = d - 79.5, y = h - 95.5, z = w - 111.5.
//
// One thread per 12 contiguous output floats (4 w positions x 3 comps),
// written as three float4 streaming stores. 672 floats per (b,d,h) row
// -> 56 chunks per row.

#define DD 160
#define HH 192
#define WW 224
#define CHUNKS_PER_ROW 56            // (WW*3)/12
#define TOTAL_CHUNKS (4 * DD * HH * CHUNKS_PER_ROW)  // 6,881,280

__global__ __launch_bounds__(256)
void AffineToDenseShift_kernel(const float* __restrict__ M,
                               float* __restrict__ out) {
    unsigned c = blockIdx.x * 256u + threadIdx.x;
    if (c >= TOTAL_CHUNKS) return;

    unsigned row = c / CHUNKS_PER_ROW;          // b*D*H + d*H + h
    unsigned wc  = c - row * CHUNKS_PER_ROW;    // chunk within row
    unsigned b   = row / (DD * HH);
    unsigned rem = row - b * (DD * HH);
    unsigned d   = rem / HH;
    unsigned h   = rem - d * HH;

    float x  = (float)d - 79.5f;
    float y  = (float)h - 95.5f;
    float w0 = (float)(wc * 4u) - 111.5f;

    const float4* Mb = (const float4*)(M + b * 12u);
    float4 r0 = __ldg(Mb + 0);   // A00 A01 A02 t0
    float4 r1 = __ldg(Mb + 1);   // A10 A11 A12 t1
    float4 r2 = __ldg(Mb + 2);   // A20 A21 A22 t2

    // Per-thread invariant parts (z term added per lane below).
    float base0 = fmaf(r0.x, x, fmaf(r0.y, y, r0.w)) - x;
    float base1 = fmaf(r1.x, x, fmaf(r1.y, y, r1.w)) - y;
    float base2 = fmaf(r2.x, x, fmaf(r2.y, y, r2.w));

    float v[12];
#pragma unroll
    for (int k = 0; k < 4; k++) {
        float z = w0 + (float)k;
        v[3 * k + 0] = fmaf(r0.z, z, base0);
        v[3 * k + 1] = fmaf(r1.z, z, base1);
        v[3 * k + 2] = fmaf(r2.z, z, base2) - z;
    }

    float4* o = (float4*)(out + (size_t)c * 12u);
    __stcs(o + 0, make_float4(v[0], v[1], v[2],  v[3]));
    __stcs(o + 1, make_float4(v[4], v[5], v[6],  v[7]));
    __stcs(o + 2, make_float4(v[8], v[9], v[10], v[11]));
}

extern "C" void kernel_launch(void* const* d_in, const int* in_sizes, int n_in,
                              void* d_out, int out_size) {
    const float* M = (const float*)d_in[0];
    float* out = (float*)d_out;
    int blocks = (TOTAL_CHUNKS + 255) / 256;   // 26880
    AffineToDenseShift_kernel<<<blocks, 256>>>(M, out);
}

// round 7
// speedup vs baseline: 1.6752x; 1.6752x over previous
#include <cuda_runtime.h>
#include <cstdint>

// Output: [B=4, D=160, H=192, W=224, 3] float32, contiguous, 330 MB.
// out[b,d,h,w,i] = A[b,i,0]*x + A[b,i,1]*y + A[b,i,2]*z + t[b,i] - mesh_i
// with x = d - 79.5, y = h - 95.5, z = w - 111.5.
//
// Each thread computes 12 contiguous floats (4 w-positions x 3 comps) into
// SMEM (3x STS.128, conflict-free: quarter-warp start offsets mod 128 cover
// all banks). Each 256-thread CTA then emits its 12,288 B contiguous tile
// with ONE 1D TMA bulk store, bypassing the L1TEX store path that was the
// 81.3% SOL bottleneck.

#define DD 160
#define HH 192
#define WW 224
#define CHUNKS_PER_ROW 56                              // (WW*3)/12
#define TOTAL_CHUNKS (4 * DD * HH * CHUNKS_PER_ROW)    // 6,881,280
#define TILE_FLOATS 3072                               // 256 threads * 12
#define TILE_BYTES  12288

__device__ __forceinline__ uint32_t smem_u32(const void* p) {
    uint32_t a;
    asm("{ .reg .u64 t; cvta.to.shared.u64 t, %1; cvt.u32.u64 %0, t; }"
        : "=r"(a) : "l"(p));
    return a;
}

__global__ __launch_bounds__(256)
void AffineToDenseShift_kernel(const float* __restrict__ M,
                               float* __restrict__ out) {
    __shared__ __align__(128) float tile[TILE_FLOATS];

    unsigned tid = threadIdx.x;
    unsigned c = blockIdx.x * 256u + tid;   // global 12-float chunk index

    unsigned row = c / CHUNKS_PER_ROW;          // b*D*H + d*H + h
    unsigned wc  = c - row * CHUNKS_PER_ROW;    // chunk within row
    unsigned b   = row / (DD * HH);
    unsigned rem = row - b * (DD * HH);
    unsigned d   = rem / HH;
    unsigned h   = rem - d * HH;

    float x  = (float)d - 79.5f;
    float y  = (float)h - 95.5f;
    float w0 = (float)(wc * 4u) - 111.5f;

    const float4* Mb = (const float4*)(M + b * 12u);
    float4 r0 = __ldg(Mb + 0);   // A00 A01 A02 t0
    float4 r1 = __ldg(Mb + 1);   // A10 A11 A12 t1
    float4 r2 = __ldg(Mb + 2);   // A20 A21 A22 t2

    float base0 = fmaf(r0.x, x, fmaf(r0.y, y, r0.w)) - x;
    float base1 = fmaf(r1.x, x, fmaf(r1.y, y, r1.w)) - y;
    float base2 = fmaf(r2.x, x, fmaf(r2.y, y, r2.w));

    float v[12];
#pragma unroll
    for (int k = 0; k < 4; k++) {
        float z = w0 + (float)k;
        v[3 * k + 0] = fmaf(r0.z, z, base0);
        v[3 * k + 1] = fmaf(r1.z, z, base1);
        v[3 * k + 2] = fmaf(r2.z, z, base2) - z;
    }

    float4* s = (float4*)(tile + tid * 12u);
    s[0] = make_float4(v[0], v[1], v[2],  v[3]);
    s[1] = make_float4(v[4], v[5], v[6],  v[7]);
    s[2] = make_float4(v[8], v[9], v[10], v[11]);

    __syncthreads();
    // Order generic-proxy STS before the async-proxy bulk copy reads smem.
    asm volatile("fence.proxy.async.shared::cta;" ::: "memory");

    if (tid == 0) {
        uint32_t saddr = smem_u32(tile);
        uint64_t gaddr = (uint64_t)(uintptr_t)out +
                         (uint64_t)blockIdx.x * (uint64_t)TILE_BYTES;
        uint32_t nbytes = TILE_BYTES;
        asm volatile(
            "cp.async.bulk.global.shared::cta.bulk_group [%0], [%1], %2;"
            :: "l"(gaddr), "r"(saddr), "r"(nbytes) : "memory");
        asm volatile("cp.async.bulk.commit_group;" ::: "memory");
        asm volatile("cp.async.bulk.wait_group 0;" ::: "memory");
    }
}

extern "C" void kernel_launch(void* const* d_in, const int* in_sizes, int n_in,
                              void* d_out, int out_size) {
    const float* M = (const float*)d_in[0];
    float* out = (float*)d_out;
    int blocks = TOTAL_CHUNKS / 256;   // 26880, exact
    AffineToDenseShift_kernel<<<blocks, 256>>>(M, out);
}